// round 2
// baseline (speedup 1.0000x reference)
#include <cuda_runtime.h>
#include <math.h>

// ---------------------------------------------------------------------------
// TwoLayerGAT: N=50000 nodes, E=800000 edges (+N self loops)
// L1: F_in=128 -> H=4 heads x C=32 (concat -> 128), relu
// L2: 128 -> 64, 1 head
// ---------------------------------------------------------------------------

#define NMAX 50000
#define D1   128   // H1*C1
#define HH   4
#define D2   64

// scratch (device globals; no allocation allowed)
__device__ float g_h1[NMAX * D1];
__device__ float g_s1[NMAX * HH];
__device__ float g_d1[NMAX * HH];
__device__ float g_m1[NMAX * HH];
__device__ float g_den1[NMAX * HH];
__device__ float g_acc1[NMAX * D1];
__device__ float g_out1[NMAX * D1];
__device__ float g_h2[NMAX * D2];
__device__ float g_s2[NMAX];
__device__ float g_d2[NMAX];
__device__ float g_m2[NMAX];
__device__ float g_den2[NMAX];
__device__ float g_acc2[NMAX * D2];
__device__ int   g_is64;

// ---------------------------------------------------------------------------
// helpers
// ---------------------------------------------------------------------------
__device__ __forceinline__ void atomicMaxFloat(float* addr, float val) {
    // mixed-sign float max via int/uint monotonic mapping
    if (val >= 0.f) atomicMax((int*)addr, __float_as_int(val));
    else            atomicMin((unsigned int*)addr, __float_as_uint(val));
}

__device__ __forceinline__ void red4(float* p, float a, float b, float c, float d) {
    // vectorized fire-and-forget reduction (sm_90+)
    asm volatile("red.global.add.v4.f32 [%0], {%1,%2,%3,%4};"
                 :: "l"(p), "f"(a), "f"(b), "f"(c), "f"(d) : "memory");
}

__device__ __forceinline__ void get_edge(const int* e32, const long long* e64,
                                         int E, int id, int& src, int& dst) {
    if (id < E) {
        if (g_is64) { src = (int)e64[id]; dst = (int)e64[E + id]; }
        else        { src = e32[id];      dst = e32[E + id]; }
    } else {
        src = dst = id - E;   // self loop
    }
}

__device__ __forceinline__ float lrelu(float e) { return e > 0.f ? e : 0.2f * e; }

// ---------------------------------------------------------------------------
// init: zero accumulators, -inf maxes, detection flag default
// ---------------------------------------------------------------------------
__global__ void init_kernel(int N) {
    int idx = blockIdx.x * blockDim.x + threadIdx.x;
    int tot = N * D1;
    if (idx < tot)      g_acc1[idx] = 0.f;
    if (idx < N * D2)   g_acc2[idx] = 0.f;
    if (idx < N * HH) { g_m1[idx] = -INFINITY; g_den1[idx] = 0.f; }
    if (idx < N)      { g_m2[idx] = -INFINITY; g_den2[idx] = 0.f; }
    if (idx == 0)       g_is64 = 1;
}

// detect edge_index dtype: if int64, all odd 32-bit words (high halves) are 0.
__global__ void detect_kernel(const unsigned int* ei) {
    int i = blockIdx.x * blockDim.x + threadIdx.x;   // 4096 probes
    int idx = 2 * i + 1;
    if (ei[idx] != 0u) g_is64 = 0;
}

// ---------------------------------------------------------------------------
// register-tiled SGEMM: out[N,COLS] = A[N,128] @ W[128,COLS]
// block 256 thr, tile 64 rows x 64 cols, thread tile 4x4, K chunks of 32
// layer==0: A=xin, out=g_h1 ; layer==1: A=g_out1, out=g_h2
// ---------------------------------------------------------------------------
template <int COLS>
__global__ __launch_bounds__(256) void gemm_kernel(const float* __restrict__ Ain,
                                                   const float* __restrict__ W,
                                                   int N, int layer) {
    const int K = 128;
    __shared__ float xs[64][36];   // row stride 36 floats (16B aligned)
    __shared__ float ws[32][68];   // row stride 68 floats (16B aligned)

    const float* A   = (layer == 0) ? Ain : g_out1;
    float*       out = (layer == 0) ? g_h1 : g_h2;

    int tx = threadIdx.x & 15;   // col quad 0..15
    int ty = threadIdx.x >> 4;   // row quad 0..15
    int r0 = blockIdx.x * 64;
    int c0 = blockIdx.y * 64;

    float acc[4][4] = {};

    for (int kc = 0; kc < K; kc += 32) {
        int t = threadIdx.x;
        #pragma unroll
        for (int it = 0; it < 2; it++) {
            int li  = t + it * 256;       // float4 index 0..511
            int row = li >> 3;            // 8 f4 per 32-float row
            int kq  = (li & 7) * 4;
            float4 v = make_float4(0.f, 0.f, 0.f, 0.f);
            if (r0 + row < N) v = *(const float4*)&A[(r0 + row) * K + kc + kq];
            *(float4*)&xs[row][kq] = v;
        }
        #pragma unroll
        for (int it = 0; it < 2; it++) {
            int li  = t + it * 256;
            int row = li >> 4;            // 16 f4 per 64-float row
            int cq  = (li & 15) * 4;
            float4 v = *(const float4*)&W[(kc + row) * COLS + c0 + cq];
            *(float4*)&ws[row][cq] = v;
        }
        __syncthreads();

        #pragma unroll
        for (int k = 0; k < 32; k++) {
            float4 b4 = *(const float4*)&ws[k][tx * 4];
            float a0 = xs[ty * 4 + 0][k];
            float a1 = xs[ty * 4 + 1][k];
            float a2 = xs[ty * 4 + 2][k];
            float a3 = xs[ty * 4 + 3][k];
            acc[0][0] += a0 * b4.x; acc[0][1] += a0 * b4.y; acc[0][2] += a0 * b4.z; acc[0][3] += a0 * b4.w;
            acc[1][0] += a1 * b4.x; acc[1][1] += a1 * b4.y; acc[1][2] += a1 * b4.z; acc[1][3] += a1 * b4.w;
            acc[2][0] += a2 * b4.x; acc[2][1] += a2 * b4.y; acc[2][2] += a2 * b4.z; acc[2][3] += a2 * b4.w;
            acc[3][0] += a3 * b4.x; acc[3][1] += a3 * b4.y; acc[3][2] += a3 * b4.z; acc[3][3] += a3 * b4.w;
        }
        __syncthreads();
    }

    #pragma unroll
    for (int i = 0; i < 4; i++) {
        int row = r0 + ty * 4 + i;
        if (row < N) {
            float4 v = make_float4(acc[i][0], acc[i][1], acc[i][2], acc[i][3]);
            *(float4*)&out[row * COLS + c0 + tx * 4] = v;
        }
    }
}

// ---------------------------------------------------------------------------
// per-node attention scores, layer 1: warp per node, 8 lanes per head
// ---------------------------------------------------------------------------
__global__ void score1_kernel(const float* __restrict__ a_src,
                              const float* __restrict__ a_dst, int N) {
    int gw   = (blockIdx.x * blockDim.x + threadIdx.x) >> 5;
    int lane = threadIdx.x & 31;
    if (gw >= N) return;
    float4 hv = *(const float4*)&g_h1[gw * D1 + lane * 4];
    float4 as = *(const float4*)&a_src[lane * 4];   // [H,C] flat = 128 floats
    float4 ad = *(const float4*)&a_dst[lane * 4];
    float ps = hv.x * as.x + hv.y * as.y + hv.z * as.z + hv.w * as.w;
    float pd = hv.x * ad.x + hv.y * ad.y + hv.z * ad.z + hv.w * ad.w;
    #pragma unroll
    for (int off = 4; off; off >>= 1) {
        ps += __shfl_xor_sync(0xffffffffu, ps, off);
        pd += __shfl_xor_sync(0xffffffffu, pd, off);
    }
    if ((lane & 7) == 0) {
        int h = lane >> 3;
        g_s1[gw * HH + h] = ps;
        g_d1[gw * HH + h] = pd;
    }
}

// per-node scores, layer 2 (1 head of 64): warp per node, 2 floats per lane
__global__ void score2_kernel(const float* __restrict__ a_src,
                              const float* __restrict__ a_dst, int N) {
    int gw   = (blockIdx.x * blockDim.x + threadIdx.x) >> 5;
    int lane = threadIdx.x & 31;
    if (gw >= N) return;
    float2 hv = *(const float2*)&g_h2[gw * D2 + lane * 2];
    float2 as = *(const float2*)&a_src[lane * 2];
    float2 ad = *(const float2*)&a_dst[lane * 2];
    float ps = hv.x * as.x + hv.y * as.y;
    float pd = hv.x * ad.x + hv.y * ad.y;
    #pragma unroll
    for (int off = 16; off; off >>= 1) {
        ps += __shfl_xor_sync(0xffffffffu, ps, off);
        pd += __shfl_xor_sync(0xffffffffu, pd, off);
    }
    if (lane == 0) { g_s2[gw] = ps; g_d2[gw] = pd; }
}

// ---------------------------------------------------------------------------
// edge pass A: segment max of logits (atomicMax)
// ---------------------------------------------------------------------------
__global__ void edgeA1_kernel(const int* e32, const long long* e64, int E, int N) {
    int id = blockIdx.x * blockDim.x + threadIdx.x;
    if (id >= E + N) return;
    int src, dst;
    get_edge(e32, e64, E, id, src, dst);
    #pragma unroll
    for (int h = 0; h < HH; h++) {
        float e = lrelu(g_s1[src * HH + h] + g_d1[dst * HH + h]);
        atomicMaxFloat(&g_m1[dst * HH + h], e);
    }
}

__global__ void edgeA2_kernel(const int* e32, const long long* e64, int E, int N) {
    int id = blockIdx.x * blockDim.x + threadIdx.x;
    if (id >= E + N) return;
    int src, dst;
    get_edge(e32, e64, E, id, src, dst);
    float e = lrelu(g_s2[src] + g_d2[dst]);
    atomicMaxFloat(&g_m2[dst], e);
}

// ---------------------------------------------------------------------------
// edge pass B: acc[dst] += h[src]*exp(e-m[dst]); den[dst] += exp
// layer 1: warp per edge (128 floats, lane handles 4; head = lane>>3)
// ---------------------------------------------------------------------------
__global__ __launch_bounds__(256) void edgeB1_kernel(const int* e32, const long long* e64,
                                                     int E, int N) {
    int gw   = (blockIdx.x * blockDim.x + threadIdx.x) >> 5;
    int lane = threadIdx.x & 31;
    if (gw >= E + N) return;
    int src, dst;
    get_edge(e32, e64, E, gw, src, dst);
    int h = lane >> 3;
    float e  = lrelu(g_s1[src * HH + h] + g_d1[dst * HH + h]);
    float ex = __expf(e - g_m1[dst * HH + h]);
    if ((lane & 7) == 0) atomicAdd(&g_den1[dst * HH + h], ex);
    float4 hv = *(const float4*)&g_h1[src * D1 + lane * 4];
    red4(&g_acc1[dst * D1 + lane * 4], hv.x * ex, hv.y * ex, hv.z * ex, hv.w * ex);
}

// layer 2: 2 edges per warp (64 floats each, 16 lanes x float4)
__global__ __launch_bounds__(256) void edgeB2_kernel(const int* e32, const long long* e64,
                                                     int E, int N) {
    int tid  = blockIdx.x * blockDim.x + threadIdx.x;
    int g16  = tid >> 4;
    int l16  = threadIdx.x & 15;
    if (g16 >= E + N) return;
    int src, dst;
    get_edge(e32, e64, E, g16, src, dst);
    float e  = lrelu(g_s2[src] + g_d2[dst]);
    float ex = __expf(e - g_m2[dst]);
    if (l16 == 0) atomicAdd(&g_den2[dst], ex);
    float4 hv = *(const float4*)&g_h2[src * D2 + l16 * 4];
    red4(&g_acc2[dst * D2 + l16 * 4], hv.x * ex, hv.y * ex, hv.z * ex, hv.w * ex);
}

// ---------------------------------------------------------------------------
// finalize: normalize, bias, (relu for layer 1)
// ---------------------------------------------------------------------------
__global__ void fin1_kernel(const float* __restrict__ b1, int N) {
    int idx = blockIdx.x * blockDim.x + threadIdx.x;
    if (idx >= N * D1) return;
    int n = idx >> 7;
    int c = idx & 127;
    int h = c >> 5;
    float v = g_acc1[idx] / g_den1[n * HH + h] + b1[c];
    g_out1[idx] = v > 0.f ? v : 0.f;
}

__global__ void fin2_kernel(const float* __restrict__ b2, float* __restrict__ out, int N) {
    int idx = blockIdx.x * blockDim.x + threadIdx.x;
    if (idx >= N * D2) return;
    int n = idx >> 6;
    int c = idx & 63;
    out[idx] = g_acc2[idx] / g_den2[n] + b2[c];
}

// ---------------------------------------------------------------------------
// launch
// ---------------------------------------------------------------------------
extern "C" void kernel_launch(void* const* d_in, const int* in_sizes, int n_in,
                              void* d_out, int out_size) {
    const float*     x   = (const float*)d_in[0];
    const int*       e32 = (const int*)d_in[1];
    const long long* e64 = (const long long*)d_in[1];
    const float*     W1  = (const float*)d_in[3];
    const float*     a1s = (const float*)d_in[4];
    const float*     a1d = (const float*)d_in[5];
    const float*     b1  = (const float*)d_in[6];
    const float*     W2  = (const float*)d_in[7];
    const float*     a2s = (const float*)d_in[8];
    const float*     a2d = (const float*)d_in[9];
    const float*     b2  = (const float*)d_in[10];
    float* out = (float*)d_out;

    int N  = in_sizes[0] / 128;   // 50000
    int E  = in_sizes[1] / 2;     // 800000 (element count invariant to dtype)
    int EN = E + N;

    init_kernel<<<(N * D1 + 255) / 256, 256>>>(N);
    detect_kernel<<<16, 256>>>((const unsigned int*)d_in[1]);

    // ---- layer 1 ----
    gemm_kernel<128><<<dim3((N + 63) / 64, 2), 256>>>(x, W1, N, 0);
    score1_kernel<<<(N * 32 + 255) / 256, 256>>>(a1s, a1d, N);
    edgeA1_kernel<<<(EN + 255) / 256, 256>>>(e32, e64, E, N);
    edgeB1_kernel<<<(EN * 32 + 255) / 256, 256>>>(e32, e64, E, N);
    fin1_kernel<<<(N * D1 + 255) / 256, 256>>>(b1, N);

    // ---- layer 2 ----
    gemm_kernel<64><<<dim3((N + 63) / 64, 1), 256>>>(nullptr, W2, N, 1);
    score2_kernel<<<(N * 32 + 255) / 256, 256>>>(a2s, a2d, N);
    edgeA2_kernel<<<(EN + 255) / 256, 256>>>(e32, e64, E, N);
    edgeB2_kernel<<<(EN * 16 + 255) / 256, 256>>>(e32, e64, E, N);
    fin2_kernel<<<(N * D2 + 255) / 256, 256>>>(b2, out, N);
}

// round 3
// speedup vs baseline: 1.9886x; 1.9886x over previous
#include <cuda_runtime.h>
#include <cuda_fp16.h>
#include <math.h>

// ---------------------------------------------------------------------------
// TwoLayerGAT — CSR pull-based, fused softmax, fp16 feature storage
// N=50000 nodes, E=800000 edges (+self loops handled analytically)
// L1: 128 -> 4x32 concat(128), relu ; L2: 128 -> 64, 1 head
// ---------------------------------------------------------------------------

#define NMAX 50016
#define EMAX 800000
#define D1   128
#define HH   4
#define D2   64

// scratch (device globals; no allocation allowed)
__device__ __half g_h1h[NMAX * D1];
__device__ float  g_s1[NMAX * HH];
__device__ float  g_d1[NMAX * HH];
__device__ float  g_out1[NMAX * D1];
__device__ __half g_h2h[NMAX * D2];
__device__ float  g_s2[NMAX];
__device__ float  g_d2[NMAX];
__device__ int    g_cnt[NMAX];
__device__ int    g_off[NMAX + 1];
__device__ int    g_cur[NMAX];
__device__ int    g_part[64];
__device__ int    g_partscan[64];
__device__ int    g_esrc[EMAX];
__device__ int    g_is64;

__device__ __forceinline__ float lrelu(float e) { return e > 0.f ? e : 0.2f * e; }

__device__ __forceinline__ void get_edge(const int* e32, const long long* e64,
                                         int E, int id, int& src, int& dst) {
    if (g_is64) { src = (int)e64[id]; dst = (int)e64[E + id]; }
    else        { src = e32[id];      dst = e32[E + id]; }
}

__device__ __forceinline__ float4 half4_to_float4(uint2 u) {
    __half2 h01 = *reinterpret_cast<__half2*>(&u.x);
    __half2 h23 = *reinterpret_cast<__half2*>(&u.y);
    float2 f01 = __half22float2(h01);
    float2 f23 = __half22float2(h23);
    return make_float4(f01.x, f01.y, f23.x, f23.y);
}

// ---------------------------------------------------------------------------
// CSR build: zero -> detect -> hist -> partsum -> scanpart -> scanfinal -> scatter
// ---------------------------------------------------------------------------
__global__ void zero_kernel(int N) {
    int i = blockIdx.x * blockDim.x + threadIdx.x;
    if (i < N) g_cnt[i] = 0;
    if (i == 0) g_is64 = 1;
}

__global__ void detect_kernel(const unsigned int* ei) {
    int i = blockIdx.x * blockDim.x + threadIdx.x;   // 4096 probes
    if (ei[2 * i + 1] != 0u) g_is64 = 0;
}

__global__ void hist_kernel(const int* e32, const long long* e64, int E) {
    int id = blockIdx.x * blockDim.x + threadIdx.x;
    if (id >= E) return;
    int src, dst;
    get_edge(e32, e64, E, id, src, dst);
    atomicAdd(&g_cnt[dst], 1);
}

__global__ void partsum_kernel(int N) {
    __shared__ int sh[256];
    int b = blockIdx.x, t = threadIdx.x;
    int base = b * 1024 + t * 4;
    int s = 0;
    #pragma unroll
    for (int j = 0; j < 4; j++) { int i = base + j; if (i < N) s += g_cnt[i]; }
    sh[t] = s;
    __syncthreads();
    for (int o = 128; o; o >>= 1) {
        if (t < o) sh[t] += sh[t + o];
        __syncthreads();
    }
    if (t == 0) g_part[b] = sh[0];
}

__global__ void scanpart_kernel(int NB, int N, int E) {
    if (threadIdx.x == 0) {
        int run = 0;
        for (int i = 0; i < NB; i++) { g_partscan[i] = run; run += g_part[i]; }
        g_off[N] = E;
    }
}

__global__ void scanfinal_kernel(int N) {
    int b = blockIdx.x, t = threadIdx.x;
    int lane = t & 31, wid = t >> 5;
    int base = b * 1024 + t * 4;
    int v[4];
    int tsum = 0;
    #pragma unroll
    for (int j = 0; j < 4; j++) {
        int i = base + j;
        v[j] = (i < N) ? g_cnt[i] : 0;
        tsum += v[j];
    }
    int inc = tsum;
    #pragma unroll
    for (int o = 1; o < 32; o <<= 1) {
        int n = __shfl_up_sync(0xffffffffu, inc, o);
        if (lane >= o) inc += n;
    }
    __shared__ int wsum[8];
    if (lane == 31) wsum[wid] = inc;
    __syncthreads();
    if (t == 0) {
        int r = 0;
        #pragma unroll
        for (int i = 0; i < 8; i++) { int x = wsum[i]; wsum[i] = r; r += x; }
    }
    __syncthreads();
    int ex = g_partscan[b] + wsum[wid] + inc - tsum;
    #pragma unroll
    for (int j = 0; j < 4; j++) {
        int i = base + j;
        if (i < N) { g_off[i] = ex; g_cur[i] = ex; }
        ex += v[j];
    }
}

__global__ void scatter_kernel(const int* e32, const long long* e64, int E) {
    int id = blockIdx.x * blockDim.x + threadIdx.x;
    if (id >= E) return;
    int src, dst;
    get_edge(e32, e64, E, id, src, dst);
    int pos = atomicAdd(&g_cur[dst], 1);
    g_esrc[pos] = src;
}

// ---------------------------------------------------------------------------
// register-tiled SGEMM: out[N,COLS](fp16) = A[N,128] @ W[128,COLS]
// LAYER==0: A=xin -> g_h1h ; LAYER==1: A=g_out1 -> g_h2h
// ---------------------------------------------------------------------------
template <int COLS, int LAYER>
__global__ __launch_bounds__(256) void gemm_kernel(const float* __restrict__ Ain,
                                                   const float* __restrict__ W,
                                                   int N) {
    const int K = 128;
    __shared__ float xs[64][36];
    __shared__ float ws[32][68];

    const float* A   = (LAYER == 0) ? Ain : g_out1;
    __half*      out = (LAYER == 0) ? g_h1h : g_h2h;

    int tx = threadIdx.x & 15;
    int ty = threadIdx.x >> 4;
    int r0 = blockIdx.x * 64;
    int c0 = blockIdx.y * 64;

    float acc[4][4] = {};

    for (int kc = 0; kc < K; kc += 32) {
        int t = threadIdx.x;
        #pragma unroll
        for (int it = 0; it < 2; it++) {
            int li  = t + it * 256;
            int row = li >> 3;
            int kq  = (li & 7) * 4;
            float4 v = make_float4(0.f, 0.f, 0.f, 0.f);
            if (r0 + row < N) v = *(const float4*)&A[(r0 + row) * K + kc + kq];
            *(float4*)&xs[row][kq] = v;
        }
        #pragma unroll
        for (int it = 0; it < 2; it++) {
            int li  = t + it * 256;
            int row = li >> 4;
            int cq  = (li & 15) * 4;
            float4 v = *(const float4*)&W[(kc + row) * COLS + c0 + cq];
            *(float4*)&ws[row][cq] = v;
        }
        __syncthreads();

        #pragma unroll
        for (int k = 0; k < 32; k++) {
            float4 b4 = *(const float4*)&ws[k][tx * 4];
            float a0 = xs[ty * 4 + 0][k];
            float a1 = xs[ty * 4 + 1][k];
            float a2 = xs[ty * 4 + 2][k];
            float a3 = xs[ty * 4 + 3][k];
            acc[0][0] += a0 * b4.x; acc[0][1] += a0 * b4.y; acc[0][2] += a0 * b4.z; acc[0][3] += a0 * b4.w;
            acc[1][0] += a1 * b4.x; acc[1][1] += a1 * b4.y; acc[1][2] += a1 * b4.z; acc[1][3] += a1 * b4.w;
            acc[2][0] += a2 * b4.x; acc[2][1] += a2 * b4.y; acc[2][2] += a2 * b4.z; acc[2][3] += a2 * b4.w;
            acc[3][0] += a3 * b4.x; acc[3][1] += a3 * b4.y; acc[3][2] += a3 * b4.z; acc[3][3] += a3 * b4.w;
        }
        __syncthreads();
    }

    #pragma unroll
    for (int i = 0; i < 4; i++) {
        int row = r0 + ty * 4 + i;
        if (row < N) {
            __half2 p0 = __floats2half2_rn(acc[i][0], acc[i][1]);
            __half2 p1 = __floats2half2_rn(acc[i][2], acc[i][3]);
            uint2 u;
            u.x = *reinterpret_cast<unsigned int*>(&p0);
            u.y = *reinterpret_cast<unsigned int*>(&p1);
            *(uint2*)&out[row * COLS + c0 + tx * 4] = u;
        }
    }
}

// ---------------------------------------------------------------------------
// per-node attention scores
// ---------------------------------------------------------------------------
__global__ void score1_kernel(const float* __restrict__ a_src,
                              const float* __restrict__ a_dst, int N) {
    int gw   = (blockIdx.x * blockDim.x + threadIdx.x) >> 5;
    int lane = threadIdx.x & 31;
    if (gw >= N) return;
    float4 hv = half4_to_float4(*(const uint2*)&g_h1h[gw * D1 + lane * 4]);
    float4 as = *(const float4*)&a_src[lane * 4];
    float4 ad = *(const float4*)&a_dst[lane * 4];
    float ps = hv.x * as.x + hv.y * as.y + hv.z * as.z + hv.w * as.w;
    float pd = hv.x * ad.x + hv.y * ad.y + hv.z * ad.z + hv.w * ad.w;
    #pragma unroll
    for (int off = 4; off; off >>= 1) {
        ps += __shfl_xor_sync(0xffffffffu, ps, off);
        pd += __shfl_xor_sync(0xffffffffu, pd, off);
    }
    if ((lane & 7) == 0) {
        int h = lane >> 3;
        g_s1[gw * HH + h] = ps;
        g_d1[gw * HH + h] = pd;
    }
}

__global__ void score2_kernel(const float* __restrict__ a_src,
                              const float* __restrict__ a_dst, int N) {
    int gw   = (blockIdx.x * blockDim.x + threadIdx.x) >> 5;
    int lane = threadIdx.x & 31;
    if (gw >= N) return;
    __half2 hv2 = *(const __half2*)&g_h2h[gw * D2 + lane * 2];
    float2 hv = __half22float2(hv2);
    float2 as = *(const float2*)&a_src[lane * 2];
    float2 ad = *(const float2*)&a_dst[lane * 2];
    float ps = hv.x * as.x + hv.y * as.y;
    float pd = hv.x * ad.x + hv.y * ad.y;
    #pragma unroll
    for (int off = 16; off; off >>= 1) {
        ps += __shfl_xor_sync(0xffffffffu, ps, off);
        pd += __shfl_xor_sync(0xffffffffu, pd, off);
    }
    if (lane == 0) { g_s2[gw] = ps; g_d2[gw] = pd; }
}

// ---------------------------------------------------------------------------
// layer 1 aggregate: warp per dst; fused softmax (unstabilized) + bias + relu
// ---------------------------------------------------------------------------
__global__ __launch_bounds__(256) void aggr1_kernel(const float* __restrict__ b1, int N) {
    int gw   = (blockIdx.x * blockDim.x + threadIdx.x) >> 5;
    int lane = threadIdx.x & 31;
    if (gw >= N) return;
    int h = lane >> 3;

    float dd = g_d1[gw * HH + h];
    // self loop
    float w = __expf(lrelu(g_s1[gw * HH + h] + dd));
    float4 hv = half4_to_float4(*(const uint2*)&g_h1h[gw * D1 + lane * 4]);
    float4 acc = make_float4(w * hv.x, w * hv.y, w * hv.z, w * hv.w);
    float den = w;

    int beg = g_off[gw], end = g_off[gw + 1];
    #pragma unroll 2
    for (int e = beg; e < end; e++) {
        int src = g_esrc[e];
        float wv = __expf(lrelu(g_s1[src * HH + h] + dd));
        float4 v = half4_to_float4(*(const uint2*)&g_h1h[src * D1 + lane * 4]);
        acc.x += wv * v.x; acc.y += wv * v.y; acc.z += wv * v.z; acc.w += wv * v.w;
        den += wv;
    }

    float inv = 1.f / den;
    float4 bb = *(const float4*)&b1[lane * 4];
    float4 o;
    o.x = fmaxf(acc.x * inv + bb.x, 0.f);
    o.y = fmaxf(acc.y * inv + bb.y, 0.f);
    o.z = fmaxf(acc.z * inv + bb.z, 0.f);
    o.w = fmaxf(acc.w * inv + bb.w, 0.f);
    *(float4*)&g_out1[gw * D1 + lane * 4] = o;
}

// ---------------------------------------------------------------------------
// layer 2 aggregate: warp per dst, 2 edges in flight (16-lane subgroups)
// ---------------------------------------------------------------------------
__global__ __launch_bounds__(256) void aggr2_kernel(const float* __restrict__ b2,
                                                    float* __restrict__ out, int N) {
    int gw   = (blockIdx.x * blockDim.x + threadIdx.x) >> 5;
    int lane = threadIdx.x & 31;
    if (gw >= N) return;
    int sub = lane >> 4;
    int l16 = lane & 15;

    float dd = g_d2[gw];
    float4 acc = make_float4(0.f, 0.f, 0.f, 0.f);
    float den = 0.f;

    if (sub == 0) {   // self loop once
        float w = __expf(lrelu(g_s2[gw] + dd));
        float4 hv = half4_to_float4(*(const uint2*)&g_h2h[gw * D2 + l16 * 4]);
        acc = make_float4(w * hv.x, w * hv.y, w * hv.z, w * hv.w);
        den = w;
    }

    int beg = g_off[gw], end = g_off[gw + 1];
    for (int e = beg + sub; e < end; e += 2) {
        int src = g_esrc[e];
        float wv = __expf(lrelu(g_s2[src] + dd));
        float4 v = half4_to_float4(*(const uint2*)&g_h2h[src * D2 + l16 * 4]);
        acc.x += wv * v.x; acc.y += wv * v.y; acc.z += wv * v.z; acc.w += wv * v.w;
        den += wv;
    }

    acc.x += __shfl_xor_sync(0xffffffffu, acc.x, 16);
    acc.y += __shfl_xor_sync(0xffffffffu, acc.y, 16);
    acc.z += __shfl_xor_sync(0xffffffffu, acc.z, 16);
    acc.w += __shfl_xor_sync(0xffffffffu, acc.w, 16);
    den   += __shfl_xor_sync(0xffffffffu, den, 16);

    if (sub == 0) {
        float inv = 1.f / den;
        float4 bb = *(const float4*)&b2[l16 * 4];
        float4 o;
        o.x = acc.x * inv + bb.x;
        o.y = acc.y * inv + bb.y;
        o.z = acc.z * inv + bb.z;
        o.w = acc.w * inv + bb.w;
        *(float4*)&out[gw * D2 + l16 * 4] = o;
    }
}

// ---------------------------------------------------------------------------
// launch
// ---------------------------------------------------------------------------
extern "C" void kernel_launch(void* const* d_in, const int* in_sizes, int n_in,
                              void* d_out, int out_size) {
    const float*     x   = (const float*)d_in[0];
    const int*       e32 = (const int*)d_in[1];
    const long long* e64 = (const long long*)d_in[1];
    const float*     W1  = (const float*)d_in[3];
    const float*     a1s = (const float*)d_in[4];
    const float*     a1d = (const float*)d_in[5];
    const float*     b1  = (const float*)d_in[6];
    const float*     W2  = (const float*)d_in[7];
    const float*     a2s = (const float*)d_in[8];
    const float*     a2d = (const float*)d_in[9];
    const float*     b2  = (const float*)d_in[10];
    float* out = (float*)d_out;

    int N  = in_sizes[0] / 128;   // 50000
    int E  = in_sizes[1] / 2;     // 800000
    int NB = (N + 1023) / 1024;

    // CSR build
    zero_kernel<<<(N + 255) / 256, 256>>>(N);
    detect_kernel<<<16, 256>>>((const unsigned int*)d_in[1]);
    hist_kernel<<<(E + 255) / 256, 256>>>(e32, e64, E);
    partsum_kernel<<<NB, 256>>>(N);
    scanpart_kernel<<<1, 32>>>(NB, N, E);
    scanfinal_kernel<<<NB, 256>>>(N);
    scatter_kernel<<<(E + 255) / 256, 256>>>(e32, e64, E);

    // layer 1
    gemm_kernel<128, 0><<<dim3((N + 63) / 64, 2), 256>>>(x, W1, N);
    score1_kernel<<<(N * 32 + 255) / 256, 256>>>(a1s, a1d, N);
    aggr1_kernel<<<(N * 32 + 255) / 256, 256>>>(b1, N);

    // layer 2
    gemm_kernel<64, 1><<<dim3((N + 63) / 64, 1), 256>>>(nullptr, W2, N);
    score2_kernel<<<(N * 32 + 255) / 256, 256>>>(a2s, a2d, N);
    aggr2_kernel<<<(N * 32 + 255) / 256, 256>>>(b2, out, N);
}